// round 4
// baseline (speedup 1.0000x reference)
#include <cuda_runtime.h>

// ---------------------------------------------------------------------------
// 2-layer GATConv on GB300 — round 4.
// R3 fused the softmax into one edge pass per layer. R4 rebuilds both GEMMs
// with 4x8 register tiles (1.5B LDS/FMA, under the 128B/cyc crossbar) and
// fuses the layer-2 logit computation into gemm2's epilogue.
// ---------------------------------------------------------------------------

#define NN 100000

static __device__ __align__(16) float g_xl1[NN * 64];
static __device__ __align__(16) float g_as1[NN * 8];
static __device__ __align__(16) float g_ad1[NN * 8];
static __device__ __align__(16) float g_den1[NN * 8];
static __device__ __align__(16) float g_out1[NN * 64];
static __device__ __align__(16) float g_h2[NN * 40];
static __device__ __align__(16) float g_as2[NN];
static __device__ __align__(16) float g_ad2[NN];
static __device__ __align__(16) float g_den2[NN];

__device__ __forceinline__ float lrelu(float a) { return a > 0.f ? a : 0.2f * a; }

__device__ __forceinline__ void red4(float* p, float a, float b, float c, float d) {
    asm volatile("red.global.add.v4.f32 [%0], {%1,%2,%3,%4};"
                 :: "l"(p), "f"(a), "f"(b), "f"(c), "f"(d) : "memory");
}
__device__ __forceinline__ void red1(float* p, float a) {
    asm volatile("red.global.add.f32 [%0], %1;" :: "l"(p), "f"(a) : "memory");
}

// ---------------------------------------------------------------------------
// K1: zero scratch accumulators + output
// ---------------------------------------------------------------------------
__global__ void k_init(float* __restrict__ out, int N) {
    int stride = gridDim.x * blockDim.x;
    int i0 = blockIdx.x * blockDim.x + threadIdx.x;
    for (int t = i0; t < N * 64; t += stride) g_out1[t] = 0.f;
    for (int t = i0; t < N * 8; t += stride) g_den1[t] = 0.f;
    for (int t = i0; t < N; t += stride) g_den2[t] = 0.f;
    for (int t = i0; t < N * 40; t += stride) out[t] = 0.f;
}

// ---------------------------------------------------------------------------
// K2: xl1 = x @ W1  [N,64] + per-head logits. M-tile=128, 256 thr, 4x8 tiles.
// Thread (tr,tc): rows tr*4..+3, cols tc*8..+7 (= head tc exactly).
// ---------------------------------------------------------------------------
__global__ void k_gemm1(const float* __restrict__ x, const float* __restrict__ W1,
                        const float* __restrict__ a_s, const float* __restrict__ a_d, int N) {
    extern __shared__ float smem[];
    float* sW = smem;                 // [128][64]
    float* sx = smem + 128 * 64;      // [128][129] padded

    const int tid = threadIdx.x;
    const int tc = tid & 7;
    const int tr = tid >> 3;

    for (int t = tid; t < 128 * 16; t += 256)
        ((float4*)sW)[t] = ((const float4*)W1)[t];

    const int row0 = blockIdx.x * 128;
    for (int t = tid; t < 128 * 32; t += 256) {
        int r = t >> 5, kq = t & 31;
        int row = row0 + r;
        float4 v = (row < N) ? *(const float4*)(x + (size_t)row * 128 + kq * 4)
                             : make_float4(0.f, 0.f, 0.f, 0.f);
        float* p = sx + r * 129 + kq * 4;
        p[0] = v.x; p[1] = v.y; p[2] = v.z; p[3] = v.w;
    }
    __syncthreads();

    float acc[4][8];
#pragma unroll
    for (int i = 0; i < 4; i++)
#pragma unroll
        for (int j = 0; j < 8; j++) acc[i][j] = 0.f;

#pragma unroll 8
    for (int k = 0; k < 128; k++) {
        float4 w0 = *(const float4*)(sW + k * 64 + tc * 8);
        float4 w1 = *(const float4*)(sW + k * 64 + tc * 8 + 4);
#pragma unroll
        for (int i = 0; i < 4; i++) {
            float xv = sx[(tr * 4 + i) * 129 + k];
            acc[i][0] += xv * w0.x; acc[i][1] += xv * w0.y;
            acc[i][2] += xv * w0.z; acc[i][3] += xv * w0.w;
            acc[i][4] += xv * w1.x; acc[i][5] += xv * w1.y;
            acc[i][6] += xv * w1.z; acc[i][7] += xv * w1.w;
        }
    }

    float av_s[8], av_d[8];
#pragma unroll
    for (int j = 0; j < 8; j++) { av_s[j] = a_s[tc * 8 + j]; av_d[j] = a_d[tc * 8 + j]; }

#pragma unroll
    for (int i = 0; i < 4; i++) {
        int row = row0 + tr * 4 + i;
        if (row < N) {
            *(float4*)(g_xl1 + (size_t)row * 64 + tc * 8) =
                make_float4(acc[i][0], acc[i][1], acc[i][2], acc[i][3]);
            *(float4*)(g_xl1 + (size_t)row * 64 + tc * 8 + 4) =
                make_float4(acc[i][4], acc[i][5], acc[i][6], acc[i][7]);
            float ss = 0.f, sd = 0.f;
#pragma unroll
            for (int j = 0; j < 8; j++) { ss += acc[i][j] * av_s[j]; sd += acc[i][j] * av_d[j]; }
            g_as1[row * 8 + tc] = ss;
            g_ad1[row * 8 + tc] = sd;
        }
    }
}

// ---------------------------------------------------------------------------
// K3: layer-1 fused edge pass. ea = exp(lrelu(alpha)); scatter ea*xl and ea.
// ---------------------------------------------------------------------------
__global__ void k_fused1(const int* __restrict__ sp, const int* __restrict__ dp,
                         int E, int ET) {
    int t = blockIdx.x * blockDim.x + threadIdx.x;
    if (t >= ET * 16) return;
    int e = t >> 4, j = t & 15;
    int h = j >> 1;
    int s, d;
    if (e < E) { s = sp[e]; d = dp[e]; } else { s = e - E; d = s; }
    float ea = __expf(lrelu(g_as1[s * 8 + h] + g_ad1[d * 8 + h]));
    float4 v = *(const float4*)(g_xl1 + (size_t)s * 64 + j * 4);
    red4(g_out1 + (size_t)d * 64 + j * 4, v.x * ea, v.y * ea, v.z * ea, v.w * ea);
    if ((j & 1) == 0) red1(g_den1 + d * 8 + h, ea);
}

// ---------------------------------------------------------------------------
// K4: h2 = elu(out1/den1 + b1) @ W2 [N,40] + fused layer-2 logits.
// M-tile=256, 320 threads, 4x8 tiles (5 col-groups cover 40 cols exactly).
// ---------------------------------------------------------------------------
__global__ void k_gemm2(const float* __restrict__ W2, const float* __restrict__ b1v,
                        const float* __restrict__ asv, const float* __restrict__ adv, int N) {
    extern __shared__ float smem[];
    float* sW = smem;                 // [64][40]
    float* sx = smem + 64 * 40;       // [256][65] padded; reused for reductions

    const int tid = threadIdx.x;
    const int tc = tid % 5;
    const int tr = tid / 5;           // 0..63

    for (int t = tid; t < 64 * 10; t += 320)
        ((float4*)sW)[t] = ((const float4*)W2)[t];

    const int row0 = blockIdx.x * 256;
    for (int t = tid; t < 256 * 16; t += 320) {
        int r = t >> 4, kq = t & 15;
        int row = row0 + r;
        float4 v = make_float4(0.f, 0.f, 0.f, 0.f);
        if (row < N) {
            v = *(const float4*)(g_out1 + (size_t)row * 64 + kq * 4);
            float inv = 1.f / (g_den1[row * 8 + (kq >> 1)] + 1e-16f);
            v.x *= inv; v.y *= inv; v.z *= inv; v.w *= inv;
        }
        v.x += b1v[kq * 4 + 0]; v.y += b1v[kq * 4 + 1];
        v.z += b1v[kq * 4 + 2]; v.w += b1v[kq * 4 + 3];
        v.x = v.x > 0.f ? v.x : expm1f(v.x);
        v.y = v.y > 0.f ? v.y : expm1f(v.y);
        v.z = v.z > 0.f ? v.z : expm1f(v.z);
        v.w = v.w > 0.f ? v.w : expm1f(v.w);
        float* p = sx + r * 65 + kq * 4;
        p[0] = v.x; p[1] = v.y; p[2] = v.z; p[3] = v.w;
    }
    __syncthreads();

    float acc[4][8];
#pragma unroll
    for (int i = 0; i < 4; i++)
#pragma unroll
        for (int j = 0; j < 8; j++) acc[i][j] = 0.f;

#pragma unroll 8
    for (int k = 0; k < 64; k++) {
        float4 w0 = *(const float4*)(sW + k * 40 + tc * 8);
        float4 w1 = *(const float4*)(sW + k * 40 + tc * 8 + 4);
#pragma unroll
        for (int i = 0; i < 4; i++) {
            float xv = sx[(tr * 4 + i) * 65 + k];
            acc[i][0] += xv * w0.x; acc[i][1] += xv * w0.y;
            acc[i][2] += xv * w0.z; acc[i][3] += xv * w0.w;
            acc[i][4] += xv * w1.x; acc[i][5] += xv * w1.y;
            acc[i][6] += xv * w1.z; acc[i][7] += xv * w1.w;
        }
    }

    float av_s[8], av_d[8];
#pragma unroll
    for (int j = 0; j < 8; j++) { av_s[j] = asv[tc * 8 + j]; av_d[j] = adv[tc * 8 + j]; }

    // reuse sx as per-row reduction buffers (512 floats)
    __syncthreads();
    for (int t = tid; t < 512; t += 320) sx[t] = 0.f;
    __syncthreads();

#pragma unroll
    for (int i = 0; i < 4; i++) {
        int r = tr * 4 + i;
        int row = row0 + r;
        if (row < N) {
            *(float4*)(g_h2 + (size_t)row * 40 + tc * 8) =
                make_float4(acc[i][0], acc[i][1], acc[i][2], acc[i][3]);
            *(float4*)(g_h2 + (size_t)row * 40 + tc * 8 + 4) =
                make_float4(acc[i][4], acc[i][5], acc[i][6], acc[i][7]);
            float ss = 0.f, sd = 0.f;
#pragma unroll
            for (int j = 0; j < 8; j++) { ss += acc[i][j] * av_s[j]; sd += acc[i][j] * av_d[j]; }
            atomicAdd(&sx[r], ss);
            atomicAdd(&sx[256 + r], sd);
        }
    }
    __syncthreads();
    for (int t = tid; t < 256; t += 320) {
        int row = row0 + t;
        if (row < N) { g_as2[row] = sx[t]; g_ad2[row] = sx[256 + t]; }
    }
}

// ---------------------------------------------------------------------------
// K5: layer-2 fused edge pass. Scatter ea*h2 into out (unnormalized) and ea.
// ---------------------------------------------------------------------------
__global__ void k_fused2(const int* __restrict__ sp, const int* __restrict__ dp,
                         int E, int ET, float* __restrict__ out) {
    int t = blockIdx.x * blockDim.x + threadIdx.x;
    if (t >= ET * 10) return;
    unsigned int e = (unsigned int)t / 10u;
    int j = t - (int)e * 10;
    int s, d;
    if ((int)e < E) { s = sp[e]; d = dp[e]; } else { s = (int)e - E; d = s; }
    float ea = __expf(lrelu(g_as2[s] + g_ad2[d]));
    float4 v = *(const float4*)(g_h2 + (size_t)s * 40 + j * 4);
    red4(out + (size_t)d * 40 + j * 4, v.x * ea, v.y * ea, v.z * ea, v.w * ea);
    if (j == 0) red1(g_den2 + d, ea);
}

// K6: normalize output in place, add b2.
__global__ void k_out(float* __restrict__ out, const float* __restrict__ b2, int N) {
    int t = blockIdx.x * blockDim.x + threadIdx.x;
    if (t >= N * 10) return;
    int n = (unsigned int)t / 10u;
    int j = t - n * 10;
    float inv = 1.f / (g_den2[n] + 1e-16f);
    float4 v = *(const float4*)(out + (size_t)n * 40 + j * 4);
    v.x = v.x * inv + b2[j * 4 + 0];
    v.y = v.y * inv + b2[j * 4 + 1];
    v.z = v.z * inv + b2[j * 4 + 2];
    v.w = v.w * inv + b2[j * 4 + 3];
    *(float4*)(out + (size_t)n * 40 + j * 4) = v;
}

// ---------------------------------------------------------------------------
extern "C" void kernel_launch(void* const* d_in, const int* in_sizes, int n_in,
                              void* d_out, int out_size) {
    const float* x = (const float*)d_in[0];
    const int* ei = (const int*)d_in[1];   // int32 (JAX x64-disabled downcast)
    const float* W1 = (const float*)d_in[2];
    const float* a_src1 = (const float*)d_in[3];
    const float* a_dst1 = (const float*)d_in[4];
    const float* b1 = (const float*)d_in[5];
    const float* W2 = (const float*)d_in[6];
    const float* a_src2 = (const float*)d_in[7];
    const float* a_dst2 = (const float*)d_in[8];
    const float* b2 = (const float*)d_in[9];
    float* out = (float*)d_out;

    const int N = in_sizes[0] / 128;
    const int E = in_sizes[1] / 2;
    const int ET = E + N;
    const int* src = ei;
    const int* dst = ei + E;

    static const int GEMM1_SMEM = (128 * 64 + 128 * 129) * (int)sizeof(float);   // 98.8KB
    static const int GEMM2_SMEM = (64 * 40 + 256 * 65) * (int)sizeof(float);     // 76.8KB
    cudaFuncSetAttribute(k_gemm1, cudaFuncAttributeMaxDynamicSharedMemorySize, GEMM1_SMEM);
    cudaFuncSetAttribute(k_gemm2, cudaFuncAttributeMaxDynamicSharedMemorySize, GEMM2_SMEM);

    k_init<<<4096, 256>>>(out, N);
    k_gemm1<<<(N + 127) / 128, 256, GEMM1_SMEM>>>(x, W1, a_src1, a_dst1, N);
    k_fused1<<<(ET * 16 + 255) / 256, 256>>>(src, dst, E, ET);
    k_gemm2<<<(N + 255) / 256, 320, GEMM2_SMEM>>>(W2, b1, a_src2, a_dst2, N);
    k_fused2<<<(ET * 10 + 255) / 256, 256>>>(src, dst, E, ET, out);
    k_out<<<(N * 10 + 255) / 256, 256>>>(out, b2, N);
}

// round 5
// speedup vs baseline: 1.0860x; 1.0860x over previous
#include <cuda_runtime.h>

// ---------------------------------------------------------------------------
// 2-layer GATConv on GB300 — round 5.
// Edge passes: R3's fused single-pass-per-layer (proven).
// GEMMs: 4x8 thread tiles, K-chunked smem (26KB/24KB -> 3-5 CTA/SM),
// packed fp32x2 FMA (fma.rn.f32x2, 2x fp32 rate on sm_103a).
// Layer-2 logits fused into gemm2 epilogue.
// ---------------------------------------------------------------------------

#define NN 100000

static __device__ __align__(16) float g_xl1[NN * 64];
static __device__ __align__(16) float g_as1[NN * 8];
static __device__ __align__(16) float g_ad1[NN * 8];
static __device__ __align__(16) float g_den1[NN * 8];
static __device__ __align__(16) float g_out1[NN * 64];
static __device__ __align__(16) float g_h2[NN * 40];
static __device__ __align__(16) float g_as2[NN];
static __device__ __align__(16) float g_ad2[NN];
static __device__ __align__(16) float g_den2[NN];

__device__ __forceinline__ float lrelu(float a) { return a > 0.f ? a : 0.2f * a; }

__device__ __forceinline__ void red4(float* p, float a, float b, float c, float d) {
    asm volatile("red.global.add.v4.f32 [%0], {%1,%2,%3,%4};"
                 :: "l"(p), "f"(a), "f"(b), "f"(c), "f"(d) : "memory");
}
__device__ __forceinline__ void red1(float* p, float a) {
    asm volatile("red.global.add.f32 [%0], %1;" :: "l"(p), "f"(a) : "memory");
}

// packed fp32x2 helpers
__device__ __forceinline__ void fma2(unsigned long long& d, unsigned long long a, unsigned long long b) {
    asm("fma.rn.f32x2 %0, %1, %2, %0;" : "+l"(d) : "l"(a), "l"(b));
}
__device__ __forceinline__ unsigned long long pack2(float v) {
    unsigned long long r;
    asm("mov.b64 %0, {%1, %2};" : "=l"(r) : "f"(v), "f"(v));
    return r;
}
__device__ __forceinline__ void unpack2(unsigned long long p, float& lo, float& hi) {
    asm("mov.b64 {%0, %1}, %2;" : "=f"(lo), "=f"(hi) : "l"(p));
}

// ---------------------------------------------------------------------------
// K1: zero scratch accumulators + output
// ---------------------------------------------------------------------------
__global__ void k_init(float* __restrict__ out, int N) {
    int stride = gridDim.x * blockDim.x;
    int i0 = blockIdx.x * blockDim.x + threadIdx.x;
    for (int t = i0; t < N * 64; t += stride) g_out1[t] = 0.f;
    for (int t = i0; t < N * 8; t += stride) g_den1[t] = 0.f;
    for (int t = i0; t < N; t += stride) g_den2[t] = 0.f;
    for (int t = i0; t < N * 40; t += stride) out[t] = 0.f;
}

// ---------------------------------------------------------------------------
// K2: xl1 = x @ W1 [N,64] + per-head logits.
// M-tile=128, 256 threads, 4 rows x 8 cols (head tc) per thread, KC=32.
// ---------------------------------------------------------------------------
__global__ void __launch_bounds__(256, 3)
k_gemm1(const float* __restrict__ x, const float* __restrict__ W1,
        const float* __restrict__ a_s, const float* __restrict__ a_d, int N) {
    __shared__ float sW[32 * 64];    // K-chunk of W1
    __shared__ float sx[128 * 36];   // x tile chunk, padded stride 36

    const int tid = threadIdx.x;
    const int tc = tid & 7;
    const int tr = tid >> 3;
    const int row0 = blockIdx.x * 128;

    unsigned long long acc[4][4];    // 4 rows x 4 col-pairs (8 cols)
#pragma unroll
    for (int i = 0; i < 4; i++)
#pragma unroll
        for (int j = 0; j < 4; j++) acc[i][j] = 0ull;

    for (int kb = 0; kb < 4; kb++) {
        // stage W chunk: rows kb*32..+31 of [128][64] (contiguous 2048 floats)
        for (int t = tid; t < 512; t += 256)
            ((float4*)sW)[t] = ((const float4*)W1)[kb * 512 + t];
        // stage x chunk: 128 rows x 32 cols
        for (int t = tid; t < 128 * 8; t += 256) {
            int r = t >> 3, q = t & 7;
            int row = row0 + r;
            float4 v = (row < N) ? *(const float4*)(x + (size_t)row * 128 + kb * 32 + q * 4)
                                 : make_float4(0.f, 0.f, 0.f, 0.f);
            *(float4*)(sx + r * 36 + q * 4) = v;
        }
        __syncthreads();

#pragma unroll 8
        for (int k = 0; k < 32; k++) {
            ulonglong2 wa = *(const ulonglong2*)(sW + k * 64 + tc * 8);
            ulonglong2 wb = *(const ulonglong2*)(sW + k * 64 + tc * 8 + 4);
#pragma unroll
            for (int i = 0; i < 4; i++) {
                unsigned long long xx = pack2(sx[(tr * 4 + i) * 36 + k]);
                fma2(acc[i][0], xx, wa.x);
                fma2(acc[i][1], xx, wa.y);
                fma2(acc[i][2], xx, wb.x);
                fma2(acc[i][3], xx, wb.y);
            }
        }
        __syncthreads();
    }

    float av_s[8], av_d[8];
#pragma unroll
    for (int j = 0; j < 8; j++) { av_s[j] = a_s[tc * 8 + j]; av_d[j] = a_d[tc * 8 + j]; }

#pragma unroll
    for (int i = 0; i < 4; i++) {
        int row = row0 + tr * 4 + i;
        if (row < N) {
            *(ulonglong2*)(g_xl1 + (size_t)row * 64 + tc * 8) =
                make_ulonglong2(acc[i][0], acc[i][1]);
            *(ulonglong2*)(g_xl1 + (size_t)row * 64 + tc * 8 + 4) =
                make_ulonglong2(acc[i][2], acc[i][3]);
            float f[8];
            unpack2(acc[i][0], f[0], f[1]); unpack2(acc[i][1], f[2], f[3]);
            unpack2(acc[i][2], f[4], f[5]); unpack2(acc[i][3], f[6], f[7]);
            float ss = 0.f, sd = 0.f;
#pragma unroll
            for (int j = 0; j < 8; j++) { ss += f[j] * av_s[j]; sd += f[j] * av_d[j]; }
            g_as1[row * 8 + tc] = ss;
            g_ad1[row * 8 + tc] = sd;
        }
    }
}

// ---------------------------------------------------------------------------
// K3: layer-1 fused edge pass. ea = exp(lrelu(alpha)); scatter ea*xl and ea.
// ---------------------------------------------------------------------------
__global__ void k_fused1(const int* __restrict__ sp, const int* __restrict__ dp,
                         int E, int ET) {
    int t = blockIdx.x * blockDim.x + threadIdx.x;
    if (t >= ET * 16) return;
    int e = t >> 4, j = t & 15;
    int h = j >> 1;
    int s, d;
    if (e < E) { s = sp[e]; d = dp[e]; } else { s = e - E; d = s; }
    float ea = __expf(lrelu(g_as1[s * 8 + h] + g_ad1[d * 8 + h]));
    float4 v = *(const float4*)(g_xl1 + (size_t)s * 64 + j * 4);
    red4(g_out1 + (size_t)d * 64 + j * 4, v.x * ea, v.y * ea, v.z * ea, v.w * ea);
    if ((j & 1) == 0) red1(g_den1 + d * 8 + h, ea);
}

// ---------------------------------------------------------------------------
// K4: h2 = elu(out1/den1 + b1) @ W2 [N,40] + fused layer-2 logits.
// M-tile=128, 160 threads (tc=tid%5, tr=tid/5), KC=32 (2 chunks).
// ---------------------------------------------------------------------------
__global__ void __launch_bounds__(160, 5)
k_gemm2(const float* __restrict__ W2, const float* __restrict__ b1v,
        const float* __restrict__ asv, const float* __restrict__ adv, int N) {
    __shared__ float sW[32 * 40];    // K-chunk of W2
    __shared__ float sx[128 * 36];   // elu(out1/den1+b1) chunk, stride 36
    __shared__ float sred[256];      // per-row logit reduction

    const int tid = threadIdx.x;
    const int tc = tid % 5;
    const int tr = tid / 5;          // 0..31
    const int row0 = blockIdx.x * 128;

    unsigned long long acc[4][4];
#pragma unroll
    for (int i = 0; i < 4; i++)
#pragma unroll
        for (int j = 0; j < 4; j++) acc[i][j] = 0ull;

    for (int kb = 0; kb < 2; kb++) {
        for (int t = tid; t < 320; t += 160)
            ((float4*)sW)[t] = ((const float4*)W2)[kb * 320 + t];
        for (int t = tid; t < 128 * 8; t += 160) {
            int r = t >> 3, q = t & 7;
            int row = row0 + r;
            int col = kb * 32 + q * 4;
            float4 v = make_float4(0.f, 0.f, 0.f, 0.f);
            if (row < N) {
                v = *(const float4*)(g_out1 + (size_t)row * 64 + col);
                float inv = 1.f / (g_den1[row * 8 + (col >> 3)] + 1e-16f);
                v.x *= inv; v.y *= inv; v.z *= inv; v.w *= inv;
            }
            v.x += b1v[col + 0]; v.y += b1v[col + 1];
            v.z += b1v[col + 2]; v.w += b1v[col + 3];
            v.x = v.x > 0.f ? v.x : expm1f(v.x);
            v.y = v.y > 0.f ? v.y : expm1f(v.y);
            v.z = v.z > 0.f ? v.z : expm1f(v.z);
            v.w = v.w > 0.f ? v.w : expm1f(v.w);
            *(float4*)(sx + r * 36 + q * 4) = v;
        }
        __syncthreads();

#pragma unroll 8
        for (int k = 0; k < 32; k++) {
            ulonglong2 wa = *(const ulonglong2*)(sW + k * 40 + tc * 8);
            ulonglong2 wb = *(const ulonglong2*)(sW + k * 40 + tc * 8 + 4);
#pragma unroll
            for (int i = 0; i < 4; i++) {
                unsigned long long xx = pack2(sx[(tr * 4 + i) * 36 + k]);
                fma2(acc[i][0], xx, wa.x);
                fma2(acc[i][1], xx, wa.y);
                fma2(acc[i][2], xx, wb.x);
                fma2(acc[i][3], xx, wb.y);
            }
        }
        __syncthreads();
    }

    float av_s[8], av_d[8];
#pragma unroll
    for (int j = 0; j < 8; j++) { av_s[j] = asv[tc * 8 + j]; av_d[j] = adv[tc * 8 + j]; }

    for (int t = tid; t < 256; t += 160) sred[t] = 0.f;
    __syncthreads();

#pragma unroll
    for (int i = 0; i < 4; i++) {
        int r = tr * 4 + i;
        int row = row0 + r;
        if (row < N) {
            *(ulonglong2*)(g_h2 + (size_t)row * 40 + tc * 8) =
                make_ulonglong2(acc[i][0], acc[i][1]);
            *(ulonglong2*)(g_h2 + (size_t)row * 40 + tc * 8 + 4) =
                make_ulonglong2(acc[i][2], acc[i][3]);
            float f[8];
            unpack2(acc[i][0], f[0], f[1]); unpack2(acc[i][1], f[2], f[3]);
            unpack2(acc[i][2], f[4], f[5]); unpack2(acc[i][3], f[6], f[7]);
            float ss = 0.f, sd = 0.f;
#pragma unroll
            for (int j = 0; j < 8; j++) { ss += f[j] * av_s[j]; sd += f[j] * av_d[j]; }
            atomicAdd(&sred[r], ss);
            atomicAdd(&sred[128 + r], sd);
        }
    }
    __syncthreads();
    for (int t = tid; t < 128; t += 160) {
        int row = row0 + t;
        if (row < N) { g_as2[row] = sred[t]; g_ad2[row] = sred[128 + t]; }
    }
}

// ---------------------------------------------------------------------------
// K5: layer-2 fused edge pass. Scatter ea*h2 into out (unnormalized) and ea.
// ---------------------------------------------------------------------------
__global__ void k_fused2(const int* __restrict__ sp, const int* __restrict__ dp,
                         int E, int ET, float* __restrict__ out) {
    int t = blockIdx.x * blockDim.x + threadIdx.x;
    if (t >= ET * 10) return;
    unsigned int e = (unsigned int)t / 10u;
    int j = t - (int)e * 10;
    int s, d;
    if ((int)e < E) { s = sp[e]; d = dp[e]; } else { s = (int)e - E; d = s; }
    float ea = __expf(lrelu(g_as2[s] + g_ad2[d]));
    float4 v = *(const float4*)(g_h2 + (size_t)s * 40 + j * 4);
    red4(out + (size_t)d * 40 + j * 4, v.x * ea, v.y * ea, v.z * ea, v.w * ea);
    if (j == 0) red1(g_den2 + d, ea);
}

// K6: normalize output in place, add b2.
__global__ void k_out(float* __restrict__ out, const float* __restrict__ b2, int N) {
    int t = blockIdx.x * blockDim.x + threadIdx.x;
    if (t >= N * 10) return;
    int n = (unsigned int)t / 10u;
    int j = t - n * 10;
    float inv = 1.f / (g_den2[n] + 1e-16f);
    float4 v = *(const float4*)(out + (size_t)n * 40 + j * 4);
    v.x = v.x * inv + b2[j * 4 + 0];
    v.y = v.y * inv + b2[j * 4 + 1];
    v.z = v.z * inv + b2[j * 4 + 2];
    v.w = v.w * inv + b2[j * 4 + 3];
    *(float4*)(out + (size_t)n * 40 + j * 4) = v;
}

// ---------------------------------------------------------------------------
extern "C" void kernel_launch(void* const* d_in, const int* in_sizes, int n_in,
                              void* d_out, int out_size) {
    const float* x = (const float*)d_in[0];
    const int* ei = (const int*)d_in[1];   // int32 (JAX x64-disabled downcast)
    const float* W1 = (const float*)d_in[2];
    const float* a_src1 = (const float*)d_in[3];
    const float* a_dst1 = (const float*)d_in[4];
    const float* b1 = (const float*)d_in[5];
    const float* W2 = (const float*)d_in[6];
    const float* a_src2 = (const float*)d_in[7];
    const float* a_dst2 = (const float*)d_in[8];
    const float* b2 = (const float*)d_in[9];
    float* out = (float*)d_out;

    const int N = in_sizes[0] / 128;
    const int E = in_sizes[1] / 2;
    const int ET = E + N;
    const int* src = ei;
    const int* dst = ei + E;

    k_init<<<4096, 256>>>(out, N);
    k_gemm1<<<(N + 127) / 128, 256>>>(x, W1, a_src1, a_dst1, N);
    k_fused1<<<(ET * 16 + 255) / 256, 256>>>(src, dst, E, ET);
    k_gemm2<<<(N + 127) / 128, 160>>>(W2, b1, a_src2, a_dst2, N);
    k_fused2<<<(ET * 10 + 255) / 256, 256>>>(src, dst, E, ET, out);
    k_out<<<(N * 10 + 255) / 256, 256>>>(out, b2, N);
}

// round 6
// speedup vs baseline: 1.4122x; 1.3003x over previous
#include <cuda_runtime.h>

// ---------------------------------------------------------------------------
// 2-layer GATConv on GB300 — round 6.
// NEW: dst-sorted CSR built on-device (hist + 2-level scan + scatter), then
// warp-per-dst-node gather/aggregate kernels: zero scatter atomics, in-register
// softmax denominators, normalized coalesced writes. GEMMs reverted to the
// proven R3 versions; layer-2 logits fused into gemm2's epilogue.
// ---------------------------------------------------------------------------

#define NN 100000
#define EE 1600000

static __device__ __align__(16) float g_xl1[NN * 64];
static __device__ __align__(16) float g_as1[NN * 8];
static __device__ __align__(16) float g_ad1[NN * 8];
static __device__ __align__(16) float g_out1[NN * 64];   // normalized layer-1 output
static __device__ __align__(16) float g_h2[NN * 40];
static __device__ __align__(16) float g_as2[NN];
static __device__ __align__(16) float g_ad2[NN];
static __device__ int g_cnt[NN];     // per-dst degree (real edges only)
static __device__ int g_off[NN];     // CSR offsets
static __device__ int g_pos[NN];     // scatter cursors
static __device__ int g_bsum[512];   // block sums for scan
static __device__ int g_esrc[EE];    // dst-sorted source indices

__device__ __forceinline__ float lrelu(float a) { return a > 0.f ? a : 0.2f * a; }

// ---------------------------------------------------------------------------
// Sort kernels
// ---------------------------------------------------------------------------
__global__ void k_zero(int N) {
    int i = blockIdx.x * blockDim.x + threadIdx.x;
    if (i < N) g_cnt[i] = 0;
}

__global__ void k_hist(const int* __restrict__ dp, int E) {
    int e = blockIdx.x * blockDim.x + threadIdx.x;
    if (e < E) atomicAdd(&g_cnt[dp[e]], 1);
}

// block-wise exclusive scan of g_cnt -> g_off, block totals -> g_bsum
__global__ void k_scan1(int N) {
    __shared__ int sm[256];
    int tid = threadIdx.x;
    int i = blockIdx.x * 256 + tid;
    int c = (i < N) ? g_cnt[i] : 0;
    sm[tid] = c;
    __syncthreads();
#pragma unroll
    for (int off = 1; off < 256; off <<= 1) {
        int v = (tid >= off) ? sm[tid - off] : 0;
        __syncthreads();
        sm[tid] += v;
        __syncthreads();
    }
    if (i < N) g_off[i] = sm[tid] - c;
    if (tid == 255) g_bsum[blockIdx.x] = sm[tid];
}

// single-block exclusive scan of block sums
__global__ void k_scan2(int nb) {
    __shared__ int sm[512];
    int tid = threadIdx.x;
    int v = (tid < nb) ? g_bsum[tid] : 0;
    sm[tid] = v;
    __syncthreads();
#pragma unroll
    for (int off = 1; off < 512; off <<= 1) {
        int u = (tid >= off) ? sm[tid - off] : 0;
        __syncthreads();
        sm[tid] += u;
        __syncthreads();
    }
    if (tid < nb) g_bsum[tid] = sm[tid] - v;
}

__global__ void k_scan3(int N) {
    int i = blockIdx.x * blockDim.x + threadIdx.x;
    if (i < N) {
        int o = g_off[i] + g_bsum[i >> 8];
        g_off[i] = o;
        g_pos[i] = o;
    }
}

__global__ void k_scatter(const int* __restrict__ sp, const int* __restrict__ dp, int E) {
    int e = blockIdx.x * blockDim.x + threadIdx.x;
    if (e < E) {
        int p = atomicAdd(&g_pos[dp[e]], 1);
        g_esrc[p] = sp[e];
    }
}

// ---------------------------------------------------------------------------
// K-gemm1: xl1 = x @ W1 [N,64] + per-head logits (R3-proven version).
// ---------------------------------------------------------------------------
__global__ void k_gemm1(const float* __restrict__ x, const float* __restrict__ W1,
                        const float* __restrict__ a_s, const float* __restrict__ a_d, int N) {
    extern __shared__ float smem[];
    float* sW = smem;               // [128][64]
    float* sx = smem + 128 * 64;    // [64][132] padded

    const int tid = threadIdx.x;
    const int tc = tid & 15;
    const int tr = tid >> 4;

    for (int t = tid; t < 128 * 64; t += 256) sW[t] = W1[t];

    const int row0 = blockIdx.x * 64;
    for (int t = tid; t < 64 * 32; t += 256) {
        int r = t >> 5, kq = t & 31;
        int row = row0 + r;
        float4 v = (row < N) ? *(const float4*)(x + (size_t)row * 128 + kq * 4)
                             : make_float4(0.f, 0.f, 0.f, 0.f);
        float* p = sx + r * 132 + kq * 4;
        p[0] = v.x; p[1] = v.y; p[2] = v.z; p[3] = v.w;
    }
    __syncthreads();

    float acc[4][4];
#pragma unroll
    for (int i = 0; i < 4; i++)
#pragma unroll
        for (int j = 0; j < 4; j++) acc[i][j] = 0.f;

#pragma unroll 4
    for (int k = 0; k < 128; k++) {
        float4 w = *(const float4*)(sW + k * 64 + tc * 4);
#pragma unroll
        for (int i = 0; i < 4; i++) {
            float xv = sx[(tr * 4 + i) * 132 + k];
            acc[i][0] += xv * w.x; acc[i][1] += xv * w.y;
            acc[i][2] += xv * w.z; acc[i][3] += xv * w.w;
        }
    }

    float avs0 = a_s[tc * 4 + 0], avs1 = a_s[tc * 4 + 1], avs2 = a_s[tc * 4 + 2], avs3 = a_s[tc * 4 + 3];
    float avd0 = a_d[tc * 4 + 0], avd1 = a_d[tc * 4 + 1], avd2 = a_d[tc * 4 + 2], avd3 = a_d[tc * 4 + 3];

#pragma unroll
    for (int i = 0; i < 4; i++) {
        int row = row0 + tr * 4 + i;
        if (row < N) {
            *(float4*)(g_xl1 + (size_t)row * 64 + tc * 4) =
                make_float4(acc[i][0], acc[i][1], acc[i][2], acc[i][3]);
        }
        float ps = acc[i][0] * avs0 + acc[i][1] * avs1 + acc[i][2] * avs2 + acc[i][3] * avs3;
        float pd = acc[i][0] * avd0 + acc[i][1] * avd1 + acc[i][2] * avd2 + acc[i][3] * avd3;
        ps += __shfl_xor_sync(0xffffffff, ps, 1);
        pd += __shfl_xor_sync(0xffffffff, pd, 1);
        if (row < N && (tc & 1) == 0) {
            g_as1[row * 8 + (tc >> 1)] = ps;
            g_ad1[row * 8 + (tc >> 1)] = pd;
        }
    }
}

// ---------------------------------------------------------------------------
// K-agg1: warp per dst node. Gather xl1[src]*ea, in-register denominator,
// write normalized row. Self loop handled explicitly (not in CSR).
// Lane owns cols c0=lane*2, c0+1; head = lane>>2.
// ---------------------------------------------------------------------------
__global__ void __launch_bounds__(256) k_agg1(int N) {
    int w = (blockIdx.x * blockDim.x + threadIdx.x) >> 5;
    int lane = threadIdx.x & 31;
    if (w >= N) return;
    const int d = w;
    const int c0 = lane * 2;
    const int h = lane >> 2;

    const float adv = g_ad1[d * 8 + h];

    // self loop
    float ea = __expf(lrelu(g_as1[d * 8 + h] + adv));
    float2 v = *(const float2*)(g_xl1 + (size_t)d * 64 + c0);
    float a0 = ea * v.x, a1 = ea * v.y, dsum = ea;

    const int start = g_off[d];
    const int end = start + g_cnt[d];
#pragma unroll 4
    for (int i = start; i < end; i++) {
        int s = g_esrc[i];  // same addr all lanes -> broadcast, L1-hot
        float e2 = __expf(lrelu(g_as1[s * 8 + h] + adv));
        float2 vv = *(const float2*)(g_xl1 + (size_t)s * 64 + c0);
        a0 += e2 * vv.x; a1 += e2 * vv.y; dsum += e2;
    }
    float inv = 1.f / (dsum + 1e-16f);
    *(float2*)(g_out1 + (size_t)d * 64 + c0) = make_float2(a0 * inv, a1 * inv);
}

// ---------------------------------------------------------------------------
// K-gemm2: h2 = elu(out1 + b1) @ W2 [N,40] + fused layer-2 logits (R3 form).
// ---------------------------------------------------------------------------
__global__ void k_gemm2(const float* __restrict__ W2, const float* __restrict__ b1v,
                        const float* __restrict__ asv, const float* __restrict__ adv, int N) {
    __shared__ float sW[64 * 40];
    __shared__ float sx[64 * 66];
    __shared__ float sred[128];
    const int tid = threadIdx.x;

    for (int t = tid; t < 64 * 40; t += 160) sW[t] = W2[t];
    for (int t = tid; t < 128; t += 160) sred[t] = 0.f;

    const int row0 = blockIdx.x * 64;
    for (int t = tid; t < 64 * 16; t += 160) {
        int r = t >> 4, kq = t & 15;
        int row = row0 + r;
        float4 v = (row < N) ? *(const float4*)(g_out1 + (size_t)row * 64 + kq * 4)
                             : make_float4(0.f, 0.f, 0.f, 0.f);
        v.x += b1v[kq * 4 + 0]; v.y += b1v[kq * 4 + 1];
        v.z += b1v[kq * 4 + 2]; v.w += b1v[kq * 4 + 3];
        v.x = v.x > 0.f ? v.x : expm1f(v.x);
        v.y = v.y > 0.f ? v.y : expm1f(v.y);
        v.z = v.z > 0.f ? v.z : expm1f(v.z);
        v.w = v.w > 0.f ? v.w : expm1f(v.w);
        float* p = sx + r * 66 + kq * 4;
        p[0] = v.x; p[1] = v.y; p[2] = v.z; p[3] = v.w;
    }
    __syncthreads();

    const int tc = tid % 10, tr = tid / 10;
    float acc[4][4];
#pragma unroll
    for (int i = 0; i < 4; i++)
#pragma unroll
        for (int j = 0; j < 4; j++) acc[i][j] = 0.f;

#pragma unroll 4
    for (int k = 0; k < 64; k++) {
        float4 w = *(const float4*)(sW + k * 40 + tc * 4);
#pragma unroll
        for (int i = 0; i < 4; i++) {
            float xv = sx[(tr * 4 + i) * 66 + k];
            acc[i][0] += xv * w.x; acc[i][1] += xv * w.y;
            acc[i][2] += xv * w.z; acc[i][3] += xv * w.w;
        }
    }

    float av_s[4], av_d[4];
#pragma unroll
    for (int j = 0; j < 4; j++) { av_s[j] = asv[tc * 4 + j]; av_d[j] = adv[tc * 4 + j]; }

#pragma unroll
    for (int i = 0; i < 4; i++) {
        int r = tr * 4 + i;
        int row = row0 + r;
        if (row < N) {
            *(float4*)(g_h2 + (size_t)row * 40 + tc * 4) =
                make_float4(acc[i][0], acc[i][1], acc[i][2], acc[i][3]);
            float ss = 0.f, sd = 0.f;
#pragma unroll
            for (int j = 0; j < 4; j++) { ss += acc[i][j] * av_s[j]; sd += acc[i][j] * av_d[j]; }
            atomicAdd(&sred[r], ss);
            atomicAdd(&sred[64 + r], sd);
        }
    }
    __syncthreads();
    for (int t = tid; t < 64; t += 160) {
        int row = row0 + t;
        if (row < N) { g_as2[row] = sred[t]; g_ad2[row] = sred[64 + t]; }
    }
}

// ---------------------------------------------------------------------------
// K-agg2: warp per dst node, 40 cols. Writes FINAL output (normalized + b2).
// Lanes 0..19 own cols c0=lane*2, c0+1; all lanes help with ea/denominator.
// ---------------------------------------------------------------------------
__global__ void __launch_bounds__(256) k_agg2(float* __restrict__ out,
                                              const float* __restrict__ b2, int N) {
    int w = (blockIdx.x * blockDim.x + threadIdx.x) >> 5;
    int lane = threadIdx.x & 31;
    if (w >= N) return;
    const int d = w;
    const int c0 = lane * 2;
    const bool act = c0 < 40;

    const float adv = g_ad2[d];

    // self loop
    float ea = __expf(lrelu(g_as2[d] + adv));
    float a0 = 0.f, a1 = 0.f, dsum = ea;
    if (act) {
        float2 v = *(const float2*)(g_h2 + (size_t)d * 40 + c0);
        a0 = ea * v.x; a1 = ea * v.y;
    }

    const int start = g_off[d];
    const int end = start + g_cnt[d];
#pragma unroll 4
    for (int i = start; i < end; i++) {
        int s = g_esrc[i];
        float e2 = __expf(lrelu(g_as2[s] + adv));
        dsum += e2;
        if (act) {
            float2 vv = *(const float2*)(g_h2 + (size_t)s * 40 + c0);
            a0 += e2 * vv.x; a1 += e2 * vv.y;
        }
    }
    if (act) {
        float inv = 1.f / (dsum + 1e-16f);
        float2 bv = *(const float2*)(b2 + c0);
        *(float2*)(out + (size_t)d * 40 + c0) =
            make_float2(a0 * inv + bv.x, a1 * inv + bv.y);
    }
}

// ---------------------------------------------------------------------------
extern "C" void kernel_launch(void* const* d_in, const int* in_sizes, int n_in,
                              void* d_out, int out_size) {
    const float* x = (const float*)d_in[0];
    const int* ei = (const int*)d_in[1];   // int32 (JAX x64-disabled downcast)
    const float* W1 = (const float*)d_in[2];
    const float* a_src1 = (const float*)d_in[3];
    const float* a_dst1 = (const float*)d_in[4];
    const float* b1 = (const float*)d_in[5];
    const float* W2 = (const float*)d_in[6];
    const float* a_src2 = (const float*)d_in[7];
    const float* a_dst2 = (const float*)d_in[8];
    const float* b2 = (const float*)d_in[9];
    float* out = (float*)d_out;

    const int N = in_sizes[0] / 128;
    const int E = in_sizes[1] / 2;
    const int* src = ei;
    const int* dst = ei + E;
    const int nb = (N + 255) / 256;

    static const int GEMM1_SMEM = (128 * 64 + 64 * 132) * (int)sizeof(float);
    cudaFuncSetAttribute(k_gemm1, cudaFuncAttributeMaxDynamicSharedMemorySize, GEMM1_SMEM);

    // build dst-sorted CSR
    k_zero<<<nb, 256>>>(N);
    k_hist<<<(E + 255) / 256, 256>>>(dst, E);
    k_scan1<<<nb, 256>>>(N);
    k_scan2<<<1, 512>>>(nb);
    k_scan3<<<nb, 256>>>(N);
    k_scatter<<<(E + 255) / 256, 256>>>(src, dst, E);

    // layer 1
    k_gemm1<<<(N + 63) / 64, 256, GEMM1_SMEM>>>(x, W1, a_src1, a_dst1, N);
    k_agg1<<<(N * 32 + 255) / 256, 256>>>(N);

    // layer 2
    k_gemm2<<<(N + 63) / 64, 160>>>(W2, b1, a_src2, a_dst2, N);
    k_agg2<<<(N * 32 + 255) / 256, 256>>>(out, b2, N);
}